// round 14
// baseline (speedup 1.0000x reference)
#include <cuda_runtime.h>
#include <cuda_bf16.h>
#include <math.h>

// Static scratch capacities (elements). Generous for shape variants.
#define V_CAP   (1 << 22)   // g_v:      16 MB
#define SC_CAP  (1 << 22)   // g_scores: 16 MB
#define C_CAP   4096        // g_c

// ---- scratch (no allocations allowed) ----
__device__ int   g_is_f32;            // 1 = float32 inputs, 0 = bfloat16
__device__ float g_v[V_CAP];          // v[b,f] = sum_h hidden[b,h]*W[h,f]
__device__ float g_c[C_CAP];          // c[b]   = sum_h hidden[b,h]*bias[h]
__device__ float g_scores[SC_CAP];    // raw scores

// Element load valid for either dtype.
__device__ __forceinline__ float load_in(const void* p, size_t idx, int is32) {
    return is32 ? ((const float*)p)[idx]
                : __bfloat162float(((const __nv_bfloat16*)p)[idx]);
}

// ============================================================
// Kernel 0: dtype detector (capped). Samples u16 words at even
// element-16 offsets. bf16 N(0,1): exponent in [118,132] ~99%.
// f32: those words are low mantissa bits, ~uniform (~6% in band).
// ============================================================
__global__ void detect_kernel(const void* enc, long long cap_elems) {
    const unsigned short* p = (const unsigned short*)enc;
    long long lim = cap_elems / 2;              // u16 index < cap (safe both dtypes)
    if (lim > 256) lim = 256;
    int hits = 0, n = 0;
    for (long long j = 0; j < lim; j++) {
        unsigned short u = p[2 * j];
        int e = (u >> 7) & 0xFF;
        if (e >= 118 && e <= 132) hits++;
        n++;
    }
    g_is_f32 = (n == 0 || hits * 2 < n) ? 1 : 0;
}

// ============================================================
// Kernel 1: v[b,f] = sum_h hidden[b,h] * W[h,f]
// grid (ceil(F2/128), B), 128 threads, dyn smem = H floats.
// ============================================================
__global__ void proj_kernel(const void* hidden, const void* W,
                            int H, int F2, int B,
                            long long cap_h, long long cap_w) {
    extern __shared__ float sh[];               // H floats
    const int is32 = g_is_f32;
    const int b = blockIdx.y;
    const int f = blockIdx.x * 128 + threadIdx.x;

    for (int h = threadIdx.x; h < H; h += 128) {
        long long idx = (long long)b * H + h;
        sh[h] = (idx < cap_h) ? load_in(hidden, (size_t)idx, is32) : 0.f;
    }
    __syncthreads();
    if (f >= F2) return;

    float acc = 0.f;
    long long last = (long long)(H - 1) * F2 + f;
    if (last < cap_w) {                          // fast path, unguarded loop
        if (is32) {
            const float* Wf = (const float*)W;
            for (int h = 0; h < H; h++) acc += sh[h] * Wf[(size_t)h * F2 + f];
        } else {
            const __nv_bfloat16* Wb = (const __nv_bfloat16*)W;
            for (int h = 0; h < H; h++)
                acc += sh[h] * __bfloat162float(Wb[(size_t)h * F2 + f]);
        }
    } else {
        for (int h = 0; h < H; h++) {
            long long idx = (long long)h * F2 + f;
            if (idx < cap_w) acc += sh[h] * load_in(W, (size_t)idx, is32);
        }
    }
    long long vi = (long long)b * F2 + f;
    if (vi < V_CAP) g_v[vi] = acc;
}

// ============================================================
// Kernel 1b: c[b] = dot(hidden[b], bias)
// ============================================================
__global__ void bias_dot_kernel(const void* hidden, const void* bias,
                                int H, long long cap_h, long long cap_b) {
    const int is32 = g_is_f32;
    const int b = blockIdx.x;
    float acc = 0.f;
    for (int h = threadIdx.x; h < H; h += 128) {
        long long hi = (long long)b * H + h;
        float hv = (hi < cap_h) ? load_in(hidden, (size_t)hi, is32) : 0.f;
        float bv = (h < cap_b) ? load_in(bias, (size_t)h, is32) : 0.f;
        acc += hv * bv;
    }
#pragma unroll
    for (int off = 16; off; off >>= 1)
        acc += __shfl_xor_sync(0xffffffffu, acc, off);
    __shared__ float ws[4];
    if ((threadIdx.x & 31) == 0) ws[threadIdx.x >> 5] = acc;
    __syncthreads();
    if (threadIdx.x == 0 && b < C_CAP)
        g_c[b] = ws[0] + ws[1] + ws[2] + ws[3];
}

// ============================================================
// Kernel 2: scores[b,s] = dot(enc[s,b,:], v[b,:])
// grid (ceil(S/8), B), 256 threads = 8 warps, one s per warp.
// dyn smem = F2 floats (v[b] staged). Coalesced scalar loads.
// ============================================================
__global__ void score_kernel(const void* enc,
                             int F2, int B, int S, long long cap_e) {
    extern __shared__ float vsh[];              // F2 floats
    const int is32 = g_is_f32;
    const int b  = blockIdx.y;
    const int s  = blockIdx.x * 8 + (threadIdx.x >> 5);
    const int ln = threadIdx.x & 31;

    for (int i = threadIdx.x; i < F2; i += 256) {
        long long vi = (long long)b * F2 + i;
        vsh[i] = (vi < V_CAP) ? g_v[vi] : 0.f;
    }
    __syncthreads();
    if (s >= S) return;

    const long long base = ((long long)s * B + b) * F2;
    float acc = 0.f;
    if (base >= 0 && base + F2 <= cap_e) {      // fast path
        if (is32) {
            const float* p = (const float*)enc + base;
            for (int k = ln; k < F2; k += 32) acc += p[k] * vsh[k];
        } else {
            const __nv_bfloat16* p = (const __nv_bfloat16*)enc + base;
            for (int k = ln; k < F2; k += 32)
                acc += __bfloat162float(p[k]) * vsh[k];
        }
    } else {
        for (int k = ln; k < F2; k += 32) {
            long long idx = base + k;
            if (idx >= 0 && idx < cap_e)
                acc += load_in(enc, (size_t)idx, is32) * vsh[k];
        }
    }
#pragma unroll
    for (int off = 16; off; off >>= 1)
        acc += __shfl_xor_sync(0xffffffffu, acc, off);
    long long si = (long long)b * S + s;
    if (ln == 0 && si < SC_CAP) g_scores[si] = acc;
}

// ============================================================
// Kernel 3: softmax over S per batch. grid B, 256 threads,
// dyn smem = S floats. Output in detected dtype, guarded.
// ============================================================
__global__ void softmax_kernel(void* out, int S, long long out_cap) {
    extern __shared__ float sc[];               // S floats
    __shared__ float red[8];
    const int is32 = g_is_f32;
    const int b = blockIdx.x;
    const int t = threadIdx.x;
    const float c = (b < C_CAP) ? g_c[b] : 0.f;

    float m = -INFINITY;
    for (int i = t; i < S; i += 256) {
        long long si = (long long)b * S + i;
        float v = ((si < SC_CAP) ? g_scores[si] : 0.f) + c;
        sc[i] = v;
        m = fmaxf(m, v);
    }
#pragma unroll
    for (int off = 16; off; off >>= 1)
        m = fmaxf(m, __shfl_xor_sync(0xffffffffu, m, off));
    if ((t & 31) == 0) red[t >> 5] = m;
    __syncthreads();
    if (t < 8) {
        float mm = red[t];
#pragma unroll
        for (int off = 4; off; off >>= 1)
            mm = fmaxf(mm, __shfl_xor_sync(0xffu, mm, off));
        red[t] = mm;
    }
    __syncthreads();
    m = red[0];
    __syncthreads();

    float sum = 0.f;
    for (int i = t; i < S; i += 256) {
        float e = __expf(sc[i] - m);
        sc[i] = e;
        sum += e;
    }
#pragma unroll
    for (int off = 16; off; off >>= 1)
        sum += __shfl_xor_sync(0xffffffffu, sum, off);
    __shared__ float red2[8];
    if ((t & 31) == 0) red2[t >> 5] = sum;
    __syncthreads();
    if (t < 8) {
        float ss = red2[t];
#pragma unroll
        for (int off = 4; off; off >>= 1)
            ss += __shfl_xor_sync(0xffu, ss, off);
        red2[t] = ss;
    }
    __syncthreads();
    const float inv = 1.f / red2[0];

    for (int i = t; i < S; i += 256) {
        long long oi = (long long)b * S + i;
        if (oi < out_cap) {
            float r = sc[i] * inv;
            if (is32) ((float*)out)[oi] = r;
            else      ((__nv_bfloat16*)out)[oi] = __float2bfloat16(r);
        }
    }
}

// ============================================================
extern "C" void kernel_launch(void* const* d_in, const int* in_sizes, int n_in,
                              void* d_out, int out_size) {
    if (n_in < 4) return;

    // Collect sizes (clamp negatives), order 4 largest ascending by size.
    long long sz[16];
    int ord[16];
    int m = n_in > 16 ? 16 : n_in;
    for (int i = 0; i < m; i++) {
        sz[i] = in_sizes[i] > 0 ? (long long)in_sizes[i] : 0;
        ord[i] = i;
    }
    for (int i = 0; i < m; i++)
        for (int j = i + 1; j < m; j++)
            if (sz[ord[j]] < sz[ord[i]]) { int t = ord[i]; ord[i] = ord[j]; ord[j] = t; }
    int ib = ord[m - 4], ih = ord[m - 3], iw = ord[m - 2], ie = ord[m - 1];
    long long nb = sz[ib], nh = sz[ih], nw = sz[iw], ne = sz[ie];

    // Jointly solve unit (elements / f32-bytes / bf16-bytes) and shapes:
    //   H = nb/u;  nw/u == 2*H*H;  B = (nh/u)/H;  S = (ne/u)/(B*2H)
    long long H = 0, B = 0, S = 0, unit = 0;
    const long long units[3] = {1, 4, 2};
    for (int k = 0; k < 3; k++) {
        long long u = units[k];
        if (nb % u || nh % u || nw % u || ne % u) continue;
        long long Hh = nb / u;
        if (Hh <= 0 || Hh > 65536) continue;
        if (nw / u != 2 * Hh * Hh) continue;
        if ((nh / u) % Hh) continue;
        long long Bb = (nh / u) / Hh;
        if (Bb <= 0 || Bb > 65535) continue;
        long long f2 = 2 * Hh;
        if ((ne / u) % (Bb * f2)) continue;
        long long Ss = (ne / u) / (Bb * f2);
        if (Ss <= 0) continue;
        H = Hh; B = Bb; S = Ss; unit = u;
        break;
    }
    if (unit == 0) { H = 512; B = 64; S = 2048; unit = 1; }  // last resort
    const int F2 = (int)(2 * H);

    const void* bias   = d_in[ib];
    const void* hidden = d_in[ih];
    const void* W      = d_in[iw];
    const void* enc    = d_in[ie];
    long long cap_b = nb / unit, cap_h = nh / unit;
    long long cap_w = nw / unit, cap_e = ne / unit;
    long long out_cap = out_size > 0 ? (long long)out_size : 0;

    detect_kernel<<<1, 1>>>(enc, cap_e);

    dim3 g1((unsigned)((F2 + 127) / 128), (unsigned)B);
    proj_kernel<<<g1, 128, (size_t)H * 4>>>(hidden, W, (int)H, F2, (int)B,
                                            cap_h, cap_w);
    bias_dot_kernel<<<(unsigned)B, 128>>>(hidden, bias, (int)H, cap_h, cap_b);

    dim3 g2((unsigned)((S + 7) / 8), (unsigned)B);
    score_kernel<<<g2, 256, (size_t)F2 * 4>>>(enc, F2, (int)B, (int)S, cap_e);

    softmax_kernel<<<(unsigned)B, 256, (size_t)S * 4>>>(d_out, (int)S, out_cap);
}